// round 9
// baseline (speedup 1.0000x reference)
#include <cuda_runtime.h>
#include <cuda_fp16.h>
#include <cuda.h>
#include <cstdint>

// ============================================================================
// out[8192,4096] = densify(COO) @ W^T + bias
// R7: BN=256 (warp tile 64x64, 2-stage ring) to raise mma issue share;
// prep = (zero-A || convert-W) fused + REDG scatter.
// ============================================================================

static constexpr int MDIM = 8192;
static constexpr int NDIM = 4096;
static constexpr int KDIM = 4096;

static constexpr int BM = 128;
static constexpr int BN = 256;
static constexpr int BK = 128;             // per stage; 2 x 64-col SW128 blocks
static constexpr int STAGES = 2;
static constexpr int KITERS = KDIM / BK;   // 32

static constexpr int NTILES_X = NDIM / BN; // 16
static constexpr int NTILES   = (MDIM / BM) * NTILES_X;  // 1024
static constexpr int GRID     = 148;

static constexpr int NTHREADS = 288;       // 8 compute warps + 1 producer warp

// Prep kernel 1: zero-A blocks || convert-W blocks
static constexpr int ZC_BLOCKS   = 1184;
static constexpr int ZERO_BLOCKS = 448;
// Prep kernel 2: scatter
static constexpr int SC_BLOCKS   = 592;

// Device-global scratch (no allocation allowed)
__device__ __half g_A[(size_t)MDIM * KDIM];   // 64 MB densified fp16 A
__device__ __half g_W[(size_t)NDIM * KDIM];   // 32 MB fp16 weight

// ----- SMEM layout -----
static constexpr int OFF_FULL  = 0;
static constexpr int OFF_EMPTY = 32;
static constexpr int OFF_A     = 1024;
static constexpr int HALF_A    = 128 * 64 * 2;           // 16384
static constexpr int STAGE_A   = 2 * HALF_A;             // 32768
static constexpr int OFF_B     = OFF_A + STAGES * STAGE_A;   // 66560
static constexpr int HALF_B    = 256 * 64 * 2;           // 32768
static constexpr int STAGE_B   = 2 * HALF_B;             // 65536
static constexpr int SMEM_TOTAL = OFF_B + STAGES * STAGE_B;  // 197632

#define DEV_INLINE __device__ __forceinline__

DEV_INLINE uint32_t smem_u32(const void* p) {
    uint32_t a;
    asm("{ .reg .u64 t; cvta.to.shared.u64 t, %1; cvt.u32.u64 %0, t; }" : "=r"(a) : "l"(p));
    return a;
}

DEV_INLINE void mbar_init(uint32_t mbar, uint32_t count) {
    asm volatile("mbarrier.init.shared.b64 [%0], %1;" :: "r"(mbar), "r"(count) : "memory");
}

DEV_INLINE void mbar_expect_tx(uint32_t mbar, uint32_t bytes) {
    asm volatile("mbarrier.arrive.expect_tx.shared.b64 _, [%0], %1;"
                 :: "r"(mbar), "r"(bytes) : "memory");
}

DEV_INLINE void mbar_arrive(uint32_t mbar) {
    asm volatile("mbarrier.arrive.shared.b64 _, [%0];" :: "r"(mbar) : "memory");
}

DEV_INLINE void mbar_wait(uint32_t mbar, uint32_t parity) {
    asm volatile(
        "{\n\t.reg .pred P;\n\t"
        "W_%=:\n\t"
        "mbarrier.try_wait.parity.acquire.cta.shared::cta.b64 P, [%0], %1, 0x989680;\n\t"
        "@P bra.uni D_%=;\n\t"
        "bra.uni W_%=;\n\t"
        "D_%=:\n\t}"
        :: "r"(mbar), "r"(parity) : "memory");
}

DEV_INLINE void mbar_wait_relaxed(uint32_t mbar, uint32_t parity) {
    asm volatile(
        "{\n\t.reg .pred P;\n\t"
        "W_%=:\n\t"
        "mbarrier.try_wait.parity.relaxed.cta.shared::cta.b64 P, [%0], %1, 0x989680;\n\t"
        "@P bra.uni D_%=;\n\t"
        "bra.uni W_%=;\n\t"
        "D_%=:\n\t}"
        :: "r"(mbar), "r"(parity) : "memory");
}

DEV_INLINE void tma_load_2d(uint32_t dst, const CUtensorMap* map, int x, int y, uint32_t mbar) {
    asm volatile(
        "cp.async.bulk.tensor.2d.shared::cta.global.tile.mbarrier::complete_tx::bytes "
        "[%0], [%1, {%2, %3}], [%4];"
        :: "r"(dst), "l"(map), "r"(x), "r"(y), "r"(mbar) : "memory");
}

DEV_INLINE void ldsm_x4(uint32_t& r0, uint32_t& r1, uint32_t& r2, uint32_t& r3, uint32_t addr) {
    asm volatile("ldmatrix.sync.aligned.m8n8.x4.shared.b16 {%0, %1, %2, %3}, [%4];"
                 : "=r"(r0), "=r"(r1), "=r"(r2), "=r"(r3) : "r"(addr));
}

DEV_INLINE void mma_16816(float& d0, float& d1, float& d2, float& d3,
                          uint32_t a0, uint32_t a1, uint32_t a2, uint32_t a3,
                          uint32_t b0, uint32_t b1) {
    asm volatile(
        "mma.sync.aligned.m16n8k16.row.col.f32.f16.f16.f32 "
        "{%0, %1, %2, %3}, {%4, %5, %6, %7}, {%8, %9}, {%0, %1, %2, %3};"
        : "+f"(d0), "+f"(d1), "+f"(d2), "+f"(d3)
        : "r"(a0), "r"(a1), "r"(a2), "r"(a3), "r"(b0), "r"(b1));
}

DEV_INLINE void red_add_f16(__half* addr, __half v) {
    unsigned short u = __half_as_ushort(v);
    asm volatile("red.global.add.noftz.f16 [%0], %1;" :: "l"(addr), "h"(u) : "memory");
}

// ============================================================================
// Prep kernels
// ============================================================================

// zero A (blocks [0, ZERO_BLOCKS)) || convert W fp32->fp16 (rest)
__global__ void prep_zc_kernel(const float* __restrict__ w) {
    if (blockIdx.x < ZERO_BLOCKS) {
        size_t gstride = (size_t)ZERO_BLOCKS * blockDim.x;
        size_t g = (size_t)blockIdx.x * blockDim.x + threadIdx.x;
        size_t nA = (size_t)MDIM * KDIM * 2 / 16;
        uint4* pa = reinterpret_cast<uint4*>(g_A);
        uint4 z = make_uint4(0, 0, 0, 0);
        for (size_t i = g; i < nA; i += gstride) pa[i] = z;
    } else {
        size_t nblk = ZC_BLOCKS - ZERO_BLOCKS;
        size_t gstride = nblk * blockDim.x;
        size_t g = (size_t)(blockIdx.x - ZERO_BLOCKS) * blockDim.x + threadIdx.x;
        size_t nW = (size_t)NDIM * KDIM / 4;
        const float4* src = reinterpret_cast<const float4*>(w);
        __half2* dst = reinterpret_cast<__half2*>(g_W);
        for (size_t i = g; i < nW; i += gstride) {
            float4 f = src[i];
            dst[2 * i]     = __floats2half2_rn(f.x, f.y);
            dst[2 * i + 1] = __floats2half2_rn(f.z, f.w);
        }
    }
}

__global__ void scatter_kernel(const float* __restrict__ vals,
                               const int* __restrict__ rows,
                               const int* __restrict__ cols, int nnz) {
    int gstride = SC_BLOCKS * blockDim.x;
    for (int i = blockIdx.x * blockDim.x + threadIdx.x; i < nnz; i += gstride) {
        size_t idx = (size_t)__ldg(rows + i) * KDIM + __ldg(cols + i);
        red_add_f16(g_A + idx, __float2half_rn(__ldg(vals + i)));
    }
}

// ============================================================================
// Persistent GEMM: warp grid 2(m) x 4(n), warp tile 64x64, 32 mma per k16.
// ============================================================================

struct FragA { uint32_t r[4][4]; };   // 4 x m16 groups
struct FragB { uint32_t r[4][4]; };   // 4 x n16 groups

__global__ void __launch_bounds__(NTHREADS, 1) gemm_f16_kernel(
    const __grid_constant__ CUtensorMap tmA,
    const __grid_constant__ CUtensorMap tmB,
    const float* __restrict__ bias,
    float* __restrict__ out)
{
    extern __shared__ char smem[];
    uint32_t sb = smem_u32(smem);
    int tid = threadIdx.x;
    int wid = tid >> 5;
    int lid = tid & 31;

    if (tid == 0) {
        for (int s = 0; s < STAGES; s++) {
            mbar_init(sb + OFF_FULL + s * 8, 1);
            mbar_init(sb + OFF_EMPTY + s * 8, 8);
        }
    }
    __syncthreads();

    if (wid == 8) {
        // ---------------- TMA producer warp (persistent) ----------------
        if (lid == 0) {
            int stage = 0, phase = 1;
            for (int t = blockIdx.x; t < NTILES; t += GRID) {
                int m0 = (t / NTILES_X) * BM;
                int n0 = (t % NTILES_X) * BN;
                for (int it = 0; it < KITERS; ++it) {
                    int k0 = it * BK;
                    mbar_wait_relaxed(sb + OFF_EMPTY + stage * 8, phase);
                    mbar_expect_tx(sb + OFF_FULL + stage * 8, STAGE_A + STAGE_B);
                    uint32_t aDst = sb + OFF_A + stage * STAGE_A;
                    uint32_t bDst = sb + OFF_B + stage * STAGE_B;
                    tma_load_2d(aDst,          &tmA, k0,      m0, sb + OFF_FULL + stage * 8);
                    tma_load_2d(aDst + HALF_A, &tmA, k0 + 64, m0, sb + OFF_FULL + stage * 8);
                    tma_load_2d(bDst,          &tmB, k0,      n0, sb + OFF_FULL + stage * 8);
                    tma_load_2d(bDst + HALF_B, &tmB, k0 + 64, n0, sb + OFF_FULL + stage * 8);
                    if (++stage == STAGES) { stage = 0; phase ^= 1; }
                }
            }
        }
        return;
    }

    // ---------------- compute warps (persistent) ----------------
    int warp_m = wid >> 2;        // co-SMSP warps differ in warp_m
    int warp_n = wid & 3;
    int wait_pos = warp_m ? 7 : 5;

    // ldmatrix lane addressing (SW128: swz(r*128+u*16) = r*128 + ((u^(r&7))*16))
    int a_row0 = warp_m * 64 + ((lid >> 3) & 1) * 8 + (lid & 7);
    int a_kh   = lid >> 4;
    int a_x7   = lid & 7;
    int b_row0 = warp_n * 64 + (lid >> 4) * 8 + (lid & 7);
    int b_kh   = (lid >> 3) & 1;
    int b_x7   = lid & 7;

    auto load_frags = [&](int stg, int s8, FragA& fa, FragB& fb) {
        int half = s8 >> 2;
        int s4   = s8 & 3;
        uint32_t aBase = sb + OFF_A + stg * STAGE_A + half * HALF_A;
        uint32_t bBase = sb + OFF_B + stg * STAGE_B + half * HALF_B;
        #pragma unroll
        for (int im = 0; im < 4; im++) {
            int row = a_row0 + im * 16;
            uint32_t addr = aBase + row * 128 + (((s4 * 2 + a_kh) ^ a_x7) << 4);
            ldsm_x4(fa.r[im][0], fa.r[im][1], fa.r[im][2], fa.r[im][3], addr);
        }
        #pragma unroll
        for (int jn = 0; jn < 4; jn++) {
            int row = b_row0 + jn * 16;
            uint32_t addr = bBase + row * 128 + (((s4 * 2 + b_kh) ^ b_x7) << 4);
            ldsm_x4(fb.r[jn][0], fb.r[jn][1], fb.r[jn][2], fb.r[jn][3], addr);
        }
    };

    FragA fa[2];
    FragB fb[2];
    int stage = 0, phase = 0;

    mbar_wait(sb + OFF_FULL, 0);
    load_frags(0, 0, fa[0], fb[0]);

    for (int t = blockIdx.x; t < NTILES; t += GRID) {
        int m0 = (t / NTILES_X) * BM;
        int n0 = (t % NTILES_X) * BN;
        bool last_tile = (t + GRID >= NTILES);

        float c[4][8][4];   // [im][n8][reg]
        #pragma unroll
        for (int i = 0; i < 4; i++)
            #pragma unroll
            for (int j = 0; j < 8; j++)
                #pragma unroll
                for (int k = 0; k < 4; k++)
                    c[i][j][k] = 0.0f;

        for (int it = 0; it < KITERS; ++it) {
            bool has_next = !(last_tile && it == KITERS - 1);
            int ns = stage ^ 1;
            int np = stage ? (phase ^ 1) : phase;   // STAGES==2: wrap flips phase

            #pragma unroll
            for (int s8 = 0; s8 < 8; ++s8) {
                int cur = s8 & 1;
                int nxt = cur ^ 1;

                if (s8 == wait_pos && has_next)
                    mbar_wait(sb + OFF_FULL + ns * 8, np);

                if (s8 < 7) {
                    load_frags(stage, s8 + 1, fa[nxt], fb[nxt]);
                } else if (has_next) {
                    load_frags(ns, 0, fa[nxt], fb[nxt]);
                }

                #pragma unroll
                for (int im = 0; im < 4; im++)
                    #pragma unroll
                    for (int in_ = 0; in_ < 8; in_++) {
                        int j = in_ >> 1, p = (in_ & 1) * 2;
                        mma_16816(c[im][in_][0], c[im][in_][1], c[im][in_][2], c[im][in_][3],
                                  fa[cur].r[im][0], fa[cur].r[im][1],
                                  fa[cur].r[im][2], fa[cur].r[im][3],
                                  fb[cur].r[j][p], fb[cur].r[j][p + 1]);
                    }
            }
            if (lid == 0) mbar_arrive(sb + OFF_EMPTY + stage * 8);
            if (++stage == STAGES) { stage = 0; phase ^= 1; }
        }

        // ---- epilogue (producer already filling next tile) ----
        int col_base = n0 + warp_n * 64 + (lid & 3) * 2;
        int row_base = m0 + warp_m * 64 + (lid >> 2);
        #pragma unroll
        for (int in_ = 0; in_ < 8; in_++) {
            int col = col_base + in_ * 8;
            float2 b2 = *reinterpret_cast<const float2*>(bias + col);
            #pragma unroll
            for (int im = 0; im < 4; im++) {
                int r0 = row_base + im * 16;
                float2 v0 = make_float2(c[im][in_][0] + b2.x, c[im][in_][1] + b2.y);
                float2 v1 = make_float2(c[im][in_][2] + b2.x, c[im][in_][3] + b2.y);
                *reinterpret_cast<float2*>(out + (size_t)r0 * NDIM + col) = v0;
                *reinterpret_cast<float2*>(out + (size_t)(r0 + 8) * NDIM + col) = v1;
            }
        }
    }
}

// ============================================================================
// Host side
// ============================================================================

typedef CUresult (*PFN_encodeTiled_t)(
    CUtensorMap*, CUtensorMapDataType, cuuint32_t, void*,
    const cuuint64_t*, const cuuint64_t*, const cuuint32_t*, const cuuint32_t*,
    CUtensorMapInterleave, CUtensorMapSwizzle, CUtensorMapL2promotion,
    CUtensorMapFloatOOBfill);

extern "C" void kernel_launch(void* const* d_in, const int* in_sizes, int n_in,
                              void* d_out, int out_size) {
    const float* vals   = (const float*)d_in[0];
    const int*   rows   = (const int*)d_in[1];
    const int*   cols   = (const int*)d_in[2];
    const float* weight = (const float*)d_in[3];
    const float* bias   = (const float*)d_in[4];
    int nnz = in_sizes[0];

    void* pA = nullptr;
    void* pW = nullptr;
    cudaGetSymbolAddress(&pA, g_A);
    cudaGetSymbolAddress(&pW, g_W);

    PFN_encodeTiled_t encode = nullptr;
    cudaDriverEntryPointQueryResult qres;
    cudaGetDriverEntryPoint("cuTensorMapEncodeTiled", (void**)&encode,
                            cudaEnableDefault, &qres);

    CUtensorMap tmA, tmB;
    {
        cuuint64_t dims[2]    = {(cuuint64_t)KDIM, (cuuint64_t)MDIM};
        cuuint64_t strides[1] = {(cuuint64_t)KDIM * sizeof(__half)};
        cuuint32_t box[2]     = {64, (cuuint32_t)BM};
        cuuint32_t es[2]      = {1, 1};
        encode(&tmA, CU_TENSOR_MAP_DATA_TYPE_FLOAT16, 2, pA, dims, strides, box, es,
               CU_TENSOR_MAP_INTERLEAVE_NONE, CU_TENSOR_MAP_SWIZZLE_128B,
               CU_TENSOR_MAP_L2_PROMOTION_L2_128B, CU_TENSOR_MAP_FLOAT_OOB_FILL_NONE);
    }
    {
        cuuint64_t dims[2]    = {(cuuint64_t)KDIM, (cuuint64_t)NDIM};
        cuuint64_t strides[1] = {(cuuint64_t)KDIM * sizeof(__half)};
        cuuint32_t box[2]     = {64, (cuuint32_t)BN};
        cuuint32_t es[2]      = {1, 1};
        encode(&tmB, CU_TENSOR_MAP_DATA_TYPE_FLOAT16, 2, pW, dims, strides, box, es,
               CU_TENSOR_MAP_INTERLEAVE_NONE, CU_TENSOR_MAP_SWIZZLE_128B,
               CU_TENSOR_MAP_L2_PROMOTION_L2_128B, CU_TENSOR_MAP_FLOAT_OOB_FILL_NONE);
    }

    prep_zc_kernel<<<ZC_BLOCKS, 256>>>(weight);
    if (nnz > 0)
        scatter_kernel<<<SC_BLOCKS, 256>>>(vals, rows, cols, nnz);

    cudaFuncSetAttribute(gemm_f16_kernel,
                         cudaFuncAttributeMaxDynamicSharedMemorySize, SMEM_TOTAL);
    gemm_f16_kernel<<<GRID, NTHREADS, SMEM_TOTAL>>>(tmA, tmB, bias, (float*)d_out);
}

// round 10
// speedup vs baseline: 3.0518x; 3.0518x over previous
#include <cuda_runtime.h>
#include <cuda_fp16.h>
#include <cuda.h>
#include <cstdint>

// ============================================================================
// out[8192,4096] = densify(COO) @ W^T + bias
// R8: R6 base (BM=BN=128, BK=128, 3-stage TMA ring, memset+fused prep) with
// 16 compute warps (4/SMSP, warp tile 32x32, ~90 regs) for bubble coverage.
// ============================================================================

static constexpr int MDIM = 8192;
static constexpr int NDIM = 4096;
static constexpr int KDIM = 4096;

static constexpr int BM = 128;
static constexpr int BN = 128;
static constexpr int BK = 128;             // per stage; 2 x 64-col SW128 blocks
static constexpr int STAGES = 3;
static constexpr int KITERS = KDIM / BK;   // 32

static constexpr int NTILES_X = NDIM / BN; // 32
static constexpr int NTILES   = (MDIM / BM) * NTILES_X;  // 2048
static constexpr int GRID     = 148;

static constexpr int NCOMPUTE = 16;        // compute warps (4 per SMSP)
static constexpr int NTHREADS = (NCOMPUTE + 1) * 32;  // 544: +1 producer warp

// Fused prep kernel split
static constexpr int PREP_BLOCKS = 1184;
static constexpr int CONV_BLOCKS = 704;

// Device-global scratch (no allocation allowed)
__device__ __half g_A[(size_t)MDIM * KDIM];   // 64 MB densified fp16 A
__device__ __half g_W[(size_t)NDIM * KDIM];   // 32 MB fp16 weight

// ----- SMEM layout -----
static constexpr int OFF_FULL  = 0;
static constexpr int OFF_EMPTY = 32;
static constexpr int OFF_A     = 1024;
static constexpr int HALF_BYTES = 128 * 64 * 2;          // 16384
static constexpr int STAGE_A   = 2 * HALF_BYTES;         // 32768
static constexpr int OFF_B     = OFF_A + STAGES * STAGE_A;
static constexpr int STAGE_B   = 2 * HALF_BYTES;
static constexpr int SMEM_TOTAL = OFF_B + STAGES * STAGE_B;  // 197632

#define DEV_INLINE __device__ __forceinline__

DEV_INLINE uint32_t smem_u32(const void* p) {
    uint32_t a;
    asm("{ .reg .u64 t; cvta.to.shared.u64 t, %1; cvt.u32.u64 %0, t; }" : "=r"(a) : "l"(p));
    return a;
}

DEV_INLINE void mbar_init(uint32_t mbar, uint32_t count) {
    asm volatile("mbarrier.init.shared.b64 [%0], %1;" :: "r"(mbar), "r"(count) : "memory");
}

DEV_INLINE void mbar_expect_tx(uint32_t mbar, uint32_t bytes) {
    asm volatile("mbarrier.arrive.expect_tx.shared.b64 _, [%0], %1;"
                 :: "r"(mbar), "r"(bytes) : "memory");
}

DEV_INLINE void mbar_arrive(uint32_t mbar) {
    asm volatile("mbarrier.arrive.shared.b64 _, [%0];" :: "r"(mbar) : "memory");
}

DEV_INLINE void mbar_wait(uint32_t mbar, uint32_t parity) {
    asm volatile(
        "{\n\t.reg .pred P;\n\t"
        "W_%=:\n\t"
        "mbarrier.try_wait.parity.acquire.cta.shared::cta.b64 P, [%0], %1, 0x989680;\n\t"
        "@P bra.uni D_%=;\n\t"
        "bra.uni W_%=;\n\t"
        "D_%=:\n\t}"
        :: "r"(mbar), "r"(parity) : "memory");
}

DEV_INLINE void mbar_wait_relaxed(uint32_t mbar, uint32_t parity) {
    asm volatile(
        "{\n\t.reg .pred P;\n\t"
        "W_%=:\n\t"
        "mbarrier.try_wait.parity.relaxed.cta.shared::cta.b64 P, [%0], %1, 0x989680;\n\t"
        "@P bra.uni D_%=;\n\t"
        "bra.uni W_%=;\n\t"
        "D_%=:\n\t}"
        :: "r"(mbar), "r"(parity) : "memory");
}

DEV_INLINE void tma_load_2d(uint32_t dst, const CUtensorMap* map, int x, int y, uint32_t mbar) {
    asm volatile(
        "cp.async.bulk.tensor.2d.shared::cta.global.tile.mbarrier::complete_tx::bytes "
        "[%0], [%1, {%2, %3}], [%4];"
        :: "r"(dst), "l"(map), "r"(x), "r"(y), "r"(mbar) : "memory");
}

DEV_INLINE void ldsm_x4(uint32_t& r0, uint32_t& r1, uint32_t& r2, uint32_t& r3, uint32_t addr) {
    asm volatile("ldmatrix.sync.aligned.m8n8.x4.shared.b16 {%0, %1, %2, %3}, [%4];"
                 : "=r"(r0), "=r"(r1), "=r"(r2), "=r"(r3) : "r"(addr));
}

DEV_INLINE void mma_16816(float& d0, float& d1, float& d2, float& d3,
                          uint32_t a0, uint32_t a1, uint32_t a2, uint32_t a3,
                          uint32_t b0, uint32_t b1) {
    asm volatile(
        "mma.sync.aligned.m16n8k16.row.col.f32.f16.f16.f32 "
        "{%0, %1, %2, %3}, {%4, %5, %6, %7}, {%8, %9}, {%0, %1, %2, %3};"
        : "+f"(d0), "+f"(d1), "+f"(d2), "+f"(d3)
        : "r"(a0), "r"(a1), "r"(a2), "r"(a3), "r"(b0), "r"(b1));
}

DEV_INLINE void red_add_f16(__half* addr, __half v) {
    unsigned short u = __half_as_ushort(v);
    asm volatile("red.global.add.noftz.f16 [%0], %1;" :: "l"(addr), "h"(u) : "memory");
}

// ============================================================================
// Prep: A zeroed by cudaMemsetAsync; then fused W-convert || REDG scatter.
// ============================================================================

__global__ void prep_fused_kernel(const float* __restrict__ w,
                                  const float* __restrict__ vals,
                                  const int* __restrict__ rows,
                                  const int* __restrict__ cols, int nnz) {
    if (blockIdx.x < CONV_BLOCKS) {
        size_t gstride = (size_t)CONV_BLOCKS * blockDim.x;
        size_t g = (size_t)blockIdx.x * blockDim.x + threadIdx.x;
        size_t nW = (size_t)NDIM * KDIM / 4;
        const float4* src = reinterpret_cast<const float4*>(w);
        __half2* dst = reinterpret_cast<__half2*>(g_W);
        for (size_t i = g; i < nW; i += gstride) {
            float4 f = src[i];
            dst[2 * i]     = __floats2half2_rn(f.x, f.y);
            dst[2 * i + 1] = __floats2half2_rn(f.z, f.w);
        }
    } else {
        int nblk = PREP_BLOCKS - CONV_BLOCKS;
        int gstride = nblk * blockDim.x;
        int g = (blockIdx.x - CONV_BLOCKS) * blockDim.x + threadIdx.x;
        for (int i = g; i < nnz; i += gstride) {
            size_t idx = (size_t)__ldg(rows + i) * KDIM + __ldg(cols + i);
            red_add_f16(g_A + idx, __float2half_rn(__ldg(vals + i)));
        }
    }
}

// ============================================================================
// Persistent GEMM: 16 compute warps (grid 4m x 4n, warp tile 32x32) +
// 1 TMA producer warp. Co-SMSP warps (same warp_n) stagger their stage-waits.
// ============================================================================

struct FragA { uint32_t r[2][4]; };   // 2 x m16 groups
struct FragB { uint32_t r[2][4]; };   // 2 x n16 groups

__global__ void __launch_bounds__(NTHREADS, 1) gemm_f16_kernel(
    const __grid_constant__ CUtensorMap tmA,
    const __grid_constant__ CUtensorMap tmB,
    const float* __restrict__ bias,
    float* __restrict__ out)
{
    extern __shared__ char smem[];
    uint32_t sb = smem_u32(smem);
    int tid = threadIdx.x;
    int wid = tid >> 5;
    int lid = tid & 31;

    if (tid == 0) {
        for (int s = 0; s < STAGES; s++) {
            mbar_init(sb + OFF_FULL + s * 8, 1);
            mbar_init(sb + OFF_EMPTY + s * 8, NCOMPUTE);
        }
    }
    __syncthreads();

    if (wid == NCOMPUTE) {
        // ---------------- TMA producer warp (persistent) ----------------
        if (lid == 0) {
            int stage = 0, phase = 1;
            for (int t = blockIdx.x; t < NTILES; t += GRID) {
                int m0 = (t / NTILES_X) * BM;
                int n0 = (t % NTILES_X) * BN;
                for (int it = 0; it < KITERS; ++it) {
                    int k0 = it * BK;
                    mbar_wait_relaxed(sb + OFF_EMPTY + stage * 8, phase);
                    mbar_expect_tx(sb + OFF_FULL + stage * 8, STAGE_A + STAGE_B);
                    uint32_t aDst = sb + OFF_A + stage * STAGE_A;
                    uint32_t bDst = sb + OFF_B + stage * STAGE_B;
                    tma_load_2d(aDst,              &tmA, k0,      m0, sb + OFF_FULL + stage * 8);
                    tma_load_2d(aDst + HALF_BYTES, &tmA, k0 + 64, m0, sb + OFF_FULL + stage * 8);
                    tma_load_2d(bDst,              &tmB, k0,      n0, sb + OFF_FULL + stage * 8);
                    tma_load_2d(bDst + HALF_BYTES, &tmB, k0 + 64, n0, sb + OFF_FULL + stage * 8);
                    if (++stage == STAGES) { stage = 0; phase ^= 1; }
                }
            }
        }
        return;
    }

    // ---------------- compute warps (persistent) ----------------
    int warp_m = wid >> 2;        // 0..3 ; co-SMSP warps share warp_n = wid&3
    int warp_n = wid & 3;         // 0..3 == SMSP id
    int wait_pos = 2 * warp_m + 1;   // 1,3,5,7 staggered across co-SMSP warps

    // ldmatrix lane addressing (SW128: swz(r*128+u*16) = r*128 + ((u^(r&7))*16))
    int a_row0 = warp_m * 32 + ((lid >> 3) & 1) * 8 + (lid & 7);
    int a_kh   = lid >> 4;
    int a_x7   = lid & 7;
    int b_row0 = warp_n * 32 + (lid >> 4) * 8 + (lid & 7);
    int b_kh   = (lid >> 3) & 1;
    int b_x7   = lid & 7;

    auto load_frags = [&](int stg, int s8, FragA& fa, FragB& fb) {
        int half = s8 >> 2;
        int s4   = s8 & 3;
        uint32_t aBase = sb + OFF_A + stg * STAGE_A + half * HALF_BYTES;
        uint32_t bBase = sb + OFF_B + stg * STAGE_B + half * HALF_BYTES;
        #pragma unroll
        for (int im = 0; im < 2; im++) {
            int row = a_row0 + im * 16;
            uint32_t addr = aBase + row * 128 + (((s4 * 2 + a_kh) ^ a_x7) << 4);
            ldsm_x4(fa.r[im][0], fa.r[im][1], fa.r[im][2], fa.r[im][3], addr);
        }
        #pragma unroll
        for (int jn = 0; jn < 2; jn++) {
            int row = b_row0 + jn * 16;
            uint32_t addr = bBase + row * 128 + (((s4 * 2 + b_kh) ^ b_x7) << 4);
            ldsm_x4(fb.r[jn][0], fb.r[jn][1], fb.r[jn][2], fb.r[jn][3], addr);
        }
    };

    FragA fa[2];
    FragB fb[2];
    int stage = 0, phase = 0;

    mbar_wait(sb + OFF_FULL, 0);
    load_frags(0, 0, fa[0], fb[0]);

    for (int t = blockIdx.x; t < NTILES; t += GRID) {
        int m0 = (t / NTILES_X) * BM;
        int n0 = (t % NTILES_X) * BN;
        bool last_tile = (t + GRID >= NTILES);

        float c[2][4][4];   // [im][n8][reg] : warp tile 32x32
        #pragma unroll
        for (int i = 0; i < 2; i++)
            #pragma unroll
            for (int j = 0; j < 4; j++)
                #pragma unroll
                for (int k = 0; k < 4; k++)
                    c[i][j][k] = 0.0f;

        for (int it = 0; it < KITERS; ++it) {
            bool has_next = !(last_tile && it == KITERS - 1);
            int ns = (stage + 1 == STAGES) ? 0 : stage + 1;
            int np = (stage + 1 == STAGES) ? (phase ^ 1) : phase;

            #pragma unroll
            for (int s8 = 0; s8 < 8; ++s8) {
                int cur = s8 & 1;
                int nxt = cur ^ 1;

                // staggered early wait for the NEXT stage
                if (s8 == wait_pos && has_next)
                    mbar_wait(sb + OFF_FULL + ns * 8, np);

                // prefetch fragments for the next k16 step
                if (s8 < 7) {
                    load_frags(stage, s8 + 1, fa[nxt], fb[nxt]);
                } else if (has_next) {
                    load_frags(ns, 0, fa[nxt], fb[nxt]);
                }

                #pragma unroll
                for (int im = 0; im < 2; im++)
                    #pragma unroll
                    for (int in_ = 0; in_ < 4; in_++) {
                        int j = in_ >> 1, p = (in_ & 1) * 2;
                        mma_16816(c[im][in_][0], c[im][in_][1], c[im][in_][2], c[im][in_][3],
                                  fa[cur].r[im][0], fa[cur].r[im][1],
                                  fa[cur].r[im][2], fa[cur].r[im][3],
                                  fb[cur].r[j][p], fb[cur].r[j][p + 1]);
                    }
            }
            if (lid == 0) mbar_arrive(sb + OFF_EMPTY + stage * 8);
            if (++stage == STAGES) { stage = 0; phase ^= 1; }
        }

        // ---- epilogue (producer already filling next tile) ----
        int col_base = n0 + warp_n * 32 + (lid & 3) * 2;
        int row_base = m0 + warp_m * 32 + (lid >> 2);
        #pragma unroll
        for (int in_ = 0; in_ < 4; in_++) {
            int col = col_base + in_ * 8;
            float2 b2 = *reinterpret_cast<const float2*>(bias + col);
            #pragma unroll
            for (int im = 0; im < 2; im++) {
                int r0 = row_base + im * 16;
                float2 v0 = make_float2(c[im][in_][0] + b2.x, c[im][in_][1] + b2.y);
                float2 v1 = make_float2(c[im][in_][2] + b2.x, c[im][in_][3] + b2.y);
                *reinterpret_cast<float2*>(out + (size_t)r0 * NDIM + col) = v0;
                *reinterpret_cast<float2*>(out + (size_t)(r0 + 8) * NDIM + col) = v1;
            }
        }
    }
}

// ============================================================================
// Host side
// ============================================================================

typedef CUresult (*PFN_encodeTiled_t)(
    CUtensorMap*, CUtensorMapDataType, cuuint32_t, void*,
    const cuuint64_t*, const cuuint64_t*, const cuuint32_t*, const cuuint32_t*,
    CUtensorMapInterleave, CUtensorMapSwizzle, CUtensorMapL2promotion,
    CUtensorMapFloatOOBfill);

extern "C" void kernel_launch(void* const* d_in, const int* in_sizes, int n_in,
                              void* d_out, int out_size) {
    const float* vals   = (const float*)d_in[0];
    const int*   rows   = (const int*)d_in[1];
    const int*   cols   = (const int*)d_in[2];
    const float* weight = (const float*)d_in[3];
    const float* bias   = (const float*)d_in[4];
    int nnz = in_sizes[0];

    void* pA = nullptr;
    void* pW = nullptr;
    cudaGetSymbolAddress(&pA, g_A);
    cudaGetSymbolAddress(&pW, g_W);

    PFN_encodeTiled_t encode = nullptr;
    cudaDriverEntryPointQueryResult qres;
    cudaGetDriverEntryPoint("cuTensorMapEncodeTiled", (void**)&encode,
                            cudaEnableDefault, &qres);

    CUtensorMap tmA, tmB;
    {
        cuuint64_t dims[2]    = {(cuuint64_t)KDIM, (cuuint64_t)MDIM};
        cuuint64_t strides[1] = {(cuuint64_t)KDIM * sizeof(__half)};
        cuuint32_t box[2]     = {64, (cuuint32_t)BM};
        cuuint32_t es[2]      = {1, 1};
        encode(&tmA, CU_TENSOR_MAP_DATA_TYPE_FLOAT16, 2, pA, dims, strides, box, es,
               CU_TENSOR_MAP_INTERLEAVE_NONE, CU_TENSOR_MAP_SWIZZLE_128B,
               CU_TENSOR_MAP_L2_PROMOTION_L2_128B, CU_TENSOR_MAP_FLOAT_OOB_FILL_NONE);
    }
    {
        cuuint64_t dims[2]    = {(cuuint64_t)KDIM, (cuuint64_t)NDIM};
        cuuint64_t strides[1] = {(cuuint64_t)KDIM * sizeof(__half)};
        cuuint32_t box[2]     = {64, (cuuint32_t)BN};
        cuuint32_t es[2]      = {1, 1};
        encode(&tmB, CU_TENSOR_MAP_DATA_TYPE_FLOAT16, 2, pW, dims, strides, box, es,
               CU_TENSOR_MAP_INTERLEAVE_NONE, CU_TENSOR_MAP_SWIZZLE_128B,
               CU_TENSOR_MAP_L2_PROMOTION_L2_128B, CU_TENSOR_MAP_FLOAT_OOB_FILL_NONE);
    }

    // zero A via driver memset (near-peak write BW, graph-capturable)
    cudaMemsetAsync(pA, 0, (size_t)MDIM * KDIM * sizeof(__half));

    // fused: W convert || COO scatter (REDG)
    prep_fused_kernel<<<PREP_BLOCKS, 256>>>(weight, vals, rows, cols, nnz);

    cudaFuncSetAttribute(gemm_f16_kernel,
                         cudaFuncAttributeMaxDynamicSharedMemorySize, SMEM_TOTAL);
    gemm_f16_kernel<<<GRID, NTHREADS, SMEM_TOTAL>>>(tmA, tmB, bias, (float*)d_out);
}

// round 13
// speedup vs baseline: 3.1456x; 1.0307x over previous
#include <cuda_runtime.h>
#include <cuda_fp16.h>
#include <cuda.h>
#include <cstdint>

// ============================================================================
// out[8192,4096] = densify(COO) @ W^T + bias
// R10: R9 (4 symmetric producer warps, one per SMSP) with the mbarrier
// protocol fixed: full barriers init with arrive count = NPROD (each
// producer's expect_tx arrives once; 4 arrivals + 64KB tx per phase).
// ============================================================================

static constexpr int MDIM = 8192;
static constexpr int NDIM = 4096;
static constexpr int KDIM = 4096;

static constexpr int BM = 128;
static constexpr int BN = 128;
static constexpr int BK = 128;             // per stage; 2 x 64-col SW128 blocks
static constexpr int STAGES = 3;
static constexpr int KITERS = KDIM / BK;   // 32

static constexpr int NTILES_X = NDIM / BN; // 32
static constexpr int NTILES   = (MDIM / BM) * NTILES_X;  // 2048
static constexpr int GRID     = 148;

static constexpr int NPROD    = 4;         // producer warps, one per SMSP
static constexpr int NTHREADS = 384;       // 8 compute + 4 producer warps

// Fused prep kernel split
static constexpr int PREP_BLOCKS = 1184;
static constexpr int CONV_BLOCKS = 704;

// Device-global scratch (no allocation allowed)
__device__ __half g_A[(size_t)MDIM * KDIM];   // 64 MB densified fp16 A
__device__ __half g_W[(size_t)NDIM * KDIM];   // 32 MB fp16 weight

// ----- SMEM layout -----
static constexpr int OFF_FULL  = 0;
static constexpr int OFF_EMPTY = 32;
static constexpr int OFF_A     = 1024;
static constexpr int HALF_BYTES = 128 * 64 * 2;          // 16384
static constexpr int STAGE_A   = 2 * HALF_BYTES;         // 32768
static constexpr int OFF_B     = OFF_A + STAGES * STAGE_A;
static constexpr int STAGE_B   = 2 * HALF_BYTES;
static constexpr int SMEM_TOTAL = OFF_B + STAGES * STAGE_B;  // 197632

#define DEV_INLINE __device__ __forceinline__

DEV_INLINE uint32_t smem_u32(const void* p) {
    uint32_t a;
    asm("{ .reg .u64 t; cvta.to.shared.u64 t, %1; cvt.u32.u64 %0, t; }" : "=r"(a) : "l"(p));
    return a;
}

DEV_INLINE void mbar_init(uint32_t mbar, uint32_t count) {
    asm volatile("mbarrier.init.shared.b64 [%0], %1;" :: "r"(mbar), "r"(count) : "memory");
}

DEV_INLINE void mbar_expect_tx(uint32_t mbar, uint32_t bytes) {
    asm volatile("mbarrier.arrive.expect_tx.shared.b64 _, [%0], %1;"
                 :: "r"(mbar), "r"(bytes) : "memory");
}

DEV_INLINE void mbar_arrive(uint32_t mbar) {
    asm volatile("mbarrier.arrive.shared.b64 _, [%0];" :: "r"(mbar) : "memory");
}

DEV_INLINE void mbar_wait(uint32_t mbar, uint32_t parity) {
    asm volatile(
        "{\n\t.reg .pred P;\n\t"
        "W_%=:\n\t"
        "mbarrier.try_wait.parity.acquire.cta.shared::cta.b64 P, [%0], %1, 0x989680;\n\t"
        "@P bra.uni D_%=;\n\t"
        "bra.uni W_%=;\n\t"
        "D_%=:\n\t}"
        :: "r"(mbar), "r"(parity) : "memory");
}

DEV_INLINE void mbar_wait_relaxed(uint32_t mbar, uint32_t parity) {
    asm volatile(
        "{\n\t.reg .pred P;\n\t"
        "W_%=:\n\t"
        "mbarrier.try_wait.parity.relaxed.cta.shared::cta.b64 P, [%0], %1, 0x989680;\n\t"
        "@P bra.uni D_%=;\n\t"
        "bra.uni W_%=;\n\t"
        "D_%=:\n\t}"
        :: "r"(mbar), "r"(parity) : "memory");
}

DEV_INLINE void tma_load_2d(uint32_t dst, const CUtensorMap* map, int x, int y, uint32_t mbar) {
    asm volatile(
        "cp.async.bulk.tensor.2d.shared::cta.global.tile.mbarrier::complete_tx::bytes "
        "[%0], [%1, {%2, %3}], [%4];"
        :: "r"(dst), "l"(map), "r"(x), "r"(y), "r"(mbar) : "memory");
}

DEV_INLINE void ldsm_x4(uint32_t& r0, uint32_t& r1, uint32_t& r2, uint32_t& r3, uint32_t addr) {
    asm volatile("ldmatrix.sync.aligned.m8n8.x4.shared.b16 {%0, %1, %2, %3}, [%4];"
                 : "=r"(r0), "=r"(r1), "=r"(r2), "=r"(r3) : "r"(addr));
}

DEV_INLINE void mma_16816(float& d0, float& d1, float& d2, float& d3,
                          uint32_t a0, uint32_t a1, uint32_t a2, uint32_t a3,
                          uint32_t b0, uint32_t b1) {
    asm volatile(
        "mma.sync.aligned.m16n8k16.row.col.f32.f16.f16.f32 "
        "{%0, %1, %2, %3}, {%4, %5, %6, %7}, {%8, %9}, {%0, %1, %2, %3};"
        : "+f"(d0), "+f"(d1), "+f"(d2), "+f"(d3)
        : "r"(a0), "r"(a1), "r"(a2), "r"(a3), "r"(b0), "r"(b1));
}

DEV_INLINE void red_add_f16(__half* addr, __half v) {
    unsigned short u = __half_as_ushort(v);
    asm volatile("red.global.add.noftz.f16 [%0], %1;" :: "l"(addr), "h"(u) : "memory");
}

// ============================================================================
// Prep: A zeroed by cudaMemsetAsync; then fused W-convert || REDG scatter.
// ============================================================================

__global__ void prep_fused_kernel(const float* __restrict__ w,
                                  const float* __restrict__ vals,
                                  const int* __restrict__ rows,
                                  const int* __restrict__ cols, int nnz) {
    if (blockIdx.x < CONV_BLOCKS) {
        size_t gstride = (size_t)CONV_BLOCKS * blockDim.x;
        size_t g = (size_t)blockIdx.x * blockDim.x + threadIdx.x;
        size_t nW = (size_t)NDIM * KDIM / 4;
        const float4* src = reinterpret_cast<const float4*>(w);
        __half2* dst = reinterpret_cast<__half2*>(g_W);
        for (size_t i = g; i < nW; i += gstride) {
            float4 f = src[i];
            dst[2 * i]     = __floats2half2_rn(f.x, f.y);
            dst[2 * i + 1] = __floats2half2_rn(f.z, f.w);
        }
    } else {
        int nblk = PREP_BLOCKS - CONV_BLOCKS;
        int gstride = nblk * blockDim.x;
        int g = (blockIdx.x - CONV_BLOCKS) * blockDim.x + threadIdx.x;
        for (int i = g; i < nnz; i += gstride) {
            size_t idx = (size_t)__ldg(rows + i) * KDIM + __ldg(cols + i);
            red_add_f16(g_A + idx, __float2half_rn(__ldg(vals + i)));
        }
    }
}

// ============================================================================
// Persistent GEMM: 8 compute warps (wid 0-7, grid 2m x 4n, tile 64x32) +
// 4 producer warps (wid 8-11, one per SMSP, each owns one TMA load/stage).
// ============================================================================

struct FragA { uint32_t r[4][4]; };
struct FragB { uint32_t r[2][4]; };

__global__ void __launch_bounds__(NTHREADS, 1) gemm_f16_kernel(
    const __grid_constant__ CUtensorMap tmA,
    const __grid_constant__ CUtensorMap tmB,
    const float* __restrict__ bias,
    float* __restrict__ out)
{
    extern __shared__ char smem[];
    uint32_t sb = smem_u32(smem);
    int tid = threadIdx.x;
    int wid = tid >> 5;
    int lid = tid & 31;

    if (tid == 0) {
        for (int s = 0; s < STAGES; s++) {
            mbar_init(sb + OFF_FULL + s * 8, NPROD);  // FIX: 4 expect_tx arrivals/phase
            mbar_init(sb + OFF_EMPTY + s * 8, 8);     // 8 compute-warp arrivals
        }
    }
    __syncthreads();

    if (wid >= 8) {
        // -------- producer warps: one per SMSP, each owns 1 of 4 loads ------
        int pw = wid - 8;   // 0..3
        if (lid == 0) {
            int stage = 0, phase = 1;
            for (int t = blockIdx.x; t < NTILES; t += GRID) {
                int m0 = (t / NTILES_X) * BM;
                int n0 = (t % NTILES_X) * BN;
                for (int it = 0; it < KITERS; ++it) {
                    int k0 = it * BK;
                    mbar_wait_relaxed(sb + OFF_EMPTY + stage * 8, phase);
                    uint32_t fullb = sb + OFF_FULL + stage * 8;
                    mbar_expect_tx(fullb, HALF_BYTES);   // arrive(1) + tx(16KB)
                    // pw 0: A k0 ; pw 1: A k0+64 ; pw 2: B k0 ; pw 3: B k0+64
                    if (pw == 0) {
                        tma_load_2d(sb + OFF_A + stage * STAGE_A, &tmA, k0, m0, fullb);
                    } else if (pw == 1) {
                        tma_load_2d(sb + OFF_A + stage * STAGE_A + HALF_BYTES, &tmA, k0 + 64, m0, fullb);
                    } else if (pw == 2) {
                        tma_load_2d(sb + OFF_B + stage * STAGE_B, &tmB, k0, n0, fullb);
                    } else {
                        tma_load_2d(sb + OFF_B + stage * STAGE_B + HALF_BYTES, &tmB, k0 + 64, n0, fullb);
                    }
                    if (++stage == STAGES) { stage = 0; phase ^= 1; }
                }
            }
        }
        return;
    }

    // ---------------- compute warps (persistent, R6 layout) ----------------
    int warp_m = wid >> 2;        // co-SMSP warps differ in warp_m
    int warp_n = wid & 3;
    int wait_pos = warp_m ? 7 : 5;

    // ldmatrix lane addressing (SW128: swz(r*128+u*16) = r*128 + ((u^(r&7))*16))
    int a_row0 = warp_m * 64 + ((lid >> 3) & 1) * 8 + (lid & 7);
    int a_kh   = lid >> 4;
    int a_x7   = lid & 7;
    int b_row0 = warp_n * 32 + (lid >> 4) * 8 + (lid & 7);
    int b_kh   = (lid >> 3) & 1;
    int b_x7   = lid & 7;

    auto load_frags = [&](int stg, int s8, FragA& fa, FragB& fb) {
        int half = s8 >> 2;
        int s4   = s8 & 3;
        uint32_t aBase = sb + OFF_A + stg * STAGE_A + half * HALF_BYTES;
        uint32_t bBase = sb + OFF_B + stg * STAGE_B + half * HALF_BYTES;
        #pragma unroll
        for (int im = 0; im < 4; im++) {
            int row = a_row0 + im * 16;
            uint32_t addr = aBase + row * 128 + (((s4 * 2 + a_kh) ^ a_x7) << 4);
            ldsm_x4(fa.r[im][0], fa.r[im][1], fa.r[im][2], fa.r[im][3], addr);
        }
        #pragma unroll
        for (int jn = 0; jn < 2; jn++) {
            int row = b_row0 + jn * 16;
            uint32_t addr = bBase + row * 128 + (((s4 * 2 + b_kh) ^ b_x7) << 4);
            ldsm_x4(fb.r[jn][0], fb.r[jn][1], fb.r[jn][2], fb.r[jn][3], addr);
        }
    };

    FragA fa[2];
    FragB fb[2];
    int stage = 0, phase = 0;

    mbar_wait(sb + OFF_FULL, 0);
    load_frags(0, 0, fa[0], fb[0]);

    for (int t = blockIdx.x; t < NTILES; t += GRID) {
        int m0 = (t / NTILES_X) * BM;
        int n0 = (t % NTILES_X) * BN;
        bool last_tile = (t + GRID >= NTILES);

        float c[4][4][4];
        #pragma unroll
        for (int i = 0; i < 4; i++)
            #pragma unroll
            for (int j = 0; j < 4; j++)
                #pragma unroll
                for (int k = 0; k < 4; k++)
                    c[i][j][k] = 0.0f;

        for (int it = 0; it < KITERS; ++it) {
            bool has_next = !(last_tile && it == KITERS - 1);
            int ns = (stage + 1 == STAGES) ? 0 : stage + 1;
            int np = (stage + 1 == STAGES) ? (phase ^ 1) : phase;

            #pragma unroll
            for (int s8 = 0; s8 < 8; ++s8) {
                int cur = s8 & 1;
                int nxt = cur ^ 1;

                if (s8 == wait_pos && has_next)
                    mbar_wait(sb + OFF_FULL + ns * 8, np);

                if (s8 < 7) {
                    load_frags(stage, s8 + 1, fa[nxt], fb[nxt]);
                } else if (has_next) {
                    load_frags(ns, 0, fa[nxt], fb[nxt]);
                }

                #pragma unroll
                for (int im = 0; im < 4; im++)
                    #pragma unroll
                    for (int in_ = 0; in_ < 4; in_++) {
                        int j = in_ >> 1, p = (in_ & 1) * 2;
                        mma_16816(c[im][in_][0], c[im][in_][1], c[im][in_][2], c[im][in_][3],
                                  fa[cur].r[im][0], fa[cur].r[im][1],
                                  fa[cur].r[im][2], fa[cur].r[im][3],
                                  fb[cur].r[j][p], fb[cur].r[j][p + 1]);
                    }
            }
            if (lid == 0) mbar_arrive(sb + OFF_EMPTY + stage * 8);
            if (++stage == STAGES) { stage = 0; phase ^= 1; }
        }

        // ---- epilogue (producers already filling next tile) ----
        int col_base = n0 + warp_n * 32 + (lid & 3) * 2;
        int row_base = m0 + warp_m * 64 + (lid >> 2);
        #pragma unroll
        for (int in_ = 0; in_ < 4; in_++) {
            int col = col_base + in_ * 8;
            float2 b2 = *reinterpret_cast<const float2*>(bias + col);
            #pragma unroll
            for (int im = 0; im < 4; im++) {
                int r0 = row_base + im * 16;
                float2 v0 = make_float2(c[im][in_][0] + b2.x, c[im][in_][1] + b2.y);
                float2 v1 = make_float2(c[im][in_][2] + b2.x, c[im][in_][3] + b2.y);
                *reinterpret_cast<float2*>(out + (size_t)r0 * NDIM + col) = v0;
                *reinterpret_cast<float2*>(out + (size_t)(r0 + 8) * NDIM + col) = v1;
            }
        }
    }
}

// ============================================================================
// Host side
// ============================================================================

typedef CUresult (*PFN_encodeTiled_t)(
    CUtensorMap*, CUtensorMapDataType, cuuint32_t, void*,
    const cuuint64_t*, const cuuint64_t*, const cuuint32_t*, const cuuint32_t*,
    CUtensorMapInterleave, CUtensorMapSwizzle, CUtensorMapL2promotion,
    CUtensorMapFloatOOBfill);

extern "C" void kernel_launch(void* const* d_in, const int* in_sizes, int n_in,
                              void* d_out, int out_size) {
    const float* vals   = (const float*)d_in[0];
    const int*   rows   = (const int*)d_in[1];
    const int*   cols   = (const int*)d_in[2];
    const float* weight = (const float*)d_in[3];
    const float* bias   = (const float*)d_in[4];
    int nnz = in_sizes[0];

    void* pA = nullptr;
    void* pW = nullptr;
    cudaGetSymbolAddress(&pA, g_A);
    cudaGetSymbolAddress(&pW, g_W);

    PFN_encodeTiled_t encode = nullptr;
    cudaDriverEntryPointQueryResult qres;
    cudaGetDriverEntryPoint("cuTensorMapEncodeTiled", (void**)&encode,
                            cudaEnableDefault, &qres);

    CUtensorMap tmA, tmB;
    {
        cuuint64_t dims[2]    = {(cuuint64_t)KDIM, (cuuint64_t)MDIM};
        cuuint64_t strides[1] = {(cuuint64_t)KDIM * sizeof(__half)};
        cuuint32_t box[2]     = {64, (cuuint32_t)BM};
        cuuint32_t es[2]      = {1, 1};
        encode(&tmA, CU_TENSOR_MAP_DATA_TYPE_FLOAT16, 2, pA, dims, strides, box, es,
               CU_TENSOR_MAP_INTERLEAVE_NONE, CU_TENSOR_MAP_SWIZZLE_128B,
               CU_TENSOR_MAP_L2_PROMOTION_L2_128B, CU_TENSOR_MAP_FLOAT_OOB_FILL_NONE);
    }
    {
        cuuint64_t dims[2]    = {(cuuint64_t)KDIM, (cuuint64_t)NDIM};
        cuuint64_t strides[1] = {(cuuint64_t)KDIM * sizeof(__half)};
        cuuint32_t box[2]     = {64, (cuuint32_t)BN};
        cuuint32_t es[2]      = {1, 1};
        encode(&tmB, CU_TENSOR_MAP_DATA_TYPE_FLOAT16, 2, pW, dims, strides, box, es,
               CU_TENSOR_MAP_INTERLEAVE_NONE, CU_TENSOR_MAP_SWIZZLE_128B,
               CU_TENSOR_MAP_L2_PROMOTION_L2_128B, CU_TENSOR_MAP_FLOAT_OOB_FILL_NONE);
    }

    // zero A via driver memset (near-peak write BW, graph-capturable)
    cudaMemsetAsync(pA, 0, (size_t)MDIM * KDIM * sizeof(__half));

    // fused: W convert || COO scatter (REDG)
    prep_fused_kernel<<<PREP_BLOCKS, 256>>>(weight, vals, rows, cols, nnz);

    cudaFuncSetAttribute(gemm_f16_kernel,
                         cudaFuncAttributeMaxDynamicSharedMemorySize, SMEM_TOTAL);
    gemm_f16_kernel<<<GRID, NTHREADS, SMEM_TOTAL>>>(tmA, tmB, bias, (float*)d_out);
}